// round 16
// baseline (speedup 1.0000x reference)
#include <cuda_runtime.h>
#include <cstdint>
#include <cstddef>
#include <math.h>

#define NB 8
#define NG 512
#define ND 384
#define NDI 768
#define NS 16
#define NR 24
#define NKC 4
#define ROWS (NB*NG)          // 4096
#define ROWS3 (3*ROWS)        // 12288
#define XRP 64                // padded xd width (real width 56)

// ---------------- scratch (device globals: no allocation allowed) ----------------
__device__ float g_h  [ROWS3*ND];
__device__ float g_h2 [ROWS3*ND];
__device__ float g_ln [ROWS3*ND];
__device__ float g_xz [ROWS3*2*NDI];
__device__ float g_xc [ROWS3*NDI];
__device__ float g_xd [ROWS3*XRP];
__device__ float g_dt [ROWS3*NDI];
__device__ float g_y  [ROWS3*NDI];
__device__ float g_mo [ROWS3*ND];
__device__ float g_cat[ROWS*3*ND];
__device__ float g_mid[ROWS*ND];
__device__ float g_xwp[12*XRP*NDI];       // zero-padded xproj weights (B/C interleaved)
__device__ float g_wip[12*2*NDI*ND];      // tf32-rounded inproj weights
__device__ float g_wop[12*ND*NDI];        // tf32-rounded outproj weights
__device__ float g_w1c[ND*3*ND];          // tf32-rounded MLP w1
__device__ float g_w2c[ND*ND];            // tf32-rounded MLP w2
__device__ int   g_ord[3*NB*NG];

// ---------------- tf32 helpers ----------------
__device__ __forceinline__ void cp_async16(float* dst, const float* src)
{
    uint32_t d = (uint32_t)__cvta_generic_to_shared(dst);
    asm volatile("cp.async.cg.shared.global [%0], [%1], 16;\n" :: "r"(d), "l"(src));
}
__device__ __forceinline__ uint32_t f2tf(float f)
{
    uint32_t u;
    asm("cvt.rna.tf32.f32 %0, %1;\n" : "=r"(u) : "f"(f));
    return u;
}
__device__ __forceinline__ float rnd_tf32(float f)
{
    return __uint_as_float(f2tf(f));
}

// ---------------- merged tf32 weight conversion (4 arrays, one launch) ----------------
#define N_WIP (12*2*NDI*ND)
#define N_WOP (12*ND*NDI)
#define N_W1  (ND*3*ND)
#define N_W2  (ND*ND)
#define N_CVT (N_WIP + N_WOP + N_W1 + N_W2)

__global__ void k_cvt_all(const float* __restrict__ a0, float* __restrict__ o0,
                          const float* __restrict__ a1, float* __restrict__ o1,
                          const float* __restrict__ a2, float* __restrict__ o2,
                          const float* __restrict__ a3, float* __restrict__ o3)
{
    int idx = blockIdx.x*256 + threadIdx.x;
    if (idx >= N_CVT) return;
    if (idx < N_WIP)                       { o0[idx] = rnd_tf32(a0[idx]); return; }
    idx -= N_WIP;
    if (idx < N_WOP)                       { o1[idx] = rnd_tf32(a1[idx]); return; }
    idx -= N_WOP;
    if (idx < N_W1)                        { o2[idx] = rnd_tf32(a2[idx]); return; }
    idx -= N_W1;
    o3[idx] = rnd_tf32(a3[idx]);
}

// ---------------- argsort (bitonic, 512 keys per (b, mix)) ----------------
__global__ void k_argsort(const float* __restrict__ center, int* __restrict__ ord)
{
    __shared__ float key[NG];
    __shared__ int   idx[NG];
    int b   = blockIdx.x;
    int mix = blockIdx.y;          // mix 0 -> axis 2 (z), 1 -> 1 (y), 2 -> 0 (x)
    int axis = 2 - mix;
    int tid = threadIdx.x;         // 256
    for (int g = tid; g < NG; g += 256) {
        key[g] = center[(b*NG + g)*3 + axis];
        idx[g] = g;
    }
    __syncthreads();
    for (int k = 2; k <= NG; k <<= 1) {
        for (int j = k >> 1; j > 0; j >>= 1) {
            for (int t = tid; t < NG; t += 256) {
                int p = t ^ j;
                if (p > t) {
                    bool up = ((t & k) == 0);
                    float a = key[t], c = key[p];
                    bool sw = up ? (a > c) : (a < c);
                    if (sw) {
                        key[t] = c; key[p] = a;
                        int ia = idx[t]; idx[t] = idx[p]; idx[p] = ia;
                    }
                }
            }
            __syncthreads();
        }
    }
    for (int g = tid; g < NG; g += 256)
        ord[(mix*NB + b)*NG + g] = idx[g];
}

// ---------------- pad + permute xproj weights: [12][56][768] -> [12][64][768] ----------------
// Output column order: 0..23 = dt rows; 24+2s = B_s, 24+2s+1 = C_s; 56..63 zero pad.
__global__ void k_padxw(const float* __restrict__ xw, float* __restrict__ xwp)
{
    int idx = blockIdx.x*256 + threadIdx.x;
    if (idx >= 12*XRP*NDI) return;
    int k = idx % NDI;
    int n = (idx / NDI) % XRP;
    int i = idx / (NDI*XRP);
    int src_n;
    if (n < 24)      src_n = n;
    else if (n < 56) { int q = n - 24; src_n = 24 + (q & 1)*16 + (q >> 1); }
    else             src_n = -1;
    xwp[idx] = (src_n >= 0) ? xw[((size_t)i*56 + src_n)*NDI + k] : 0.f;
}

// ---------------- gather (all 3 mixers) ----------------
__global__ void k_gather(const float* __restrict__ in, const int* __restrict__ ord,
                         float* __restrict__ out)
{
    int idx = blockIdx.x*256 + threadIdx.x;
    if (idx >= ROWS3*ND) return;
    int d  = idx % ND;
    int j  = (idx / ND) % NG;
    int bg = idx / (ND*NG);      // 0..23
    int b  = bg & 7;
    int mix= bg >> 3;
    int src = ord[(mix*NB + b)*NG + j];
    out[idx] = in[((size_t)(b*NG + src))*ND + d];
}

// ---------------- scatter into concat buffer ----------------
__global__ void k_scatter(const float* __restrict__ in, const int* __restrict__ ord,
                          float* __restrict__ cat)
{
    int idx = blockIdx.x*256 + threadIdx.x;
    if (idx >= ROWS3*ND) return;
    int d  = idx % ND;
    int j  = (idx / ND) % NG;
    int bg = idx / (ND*NG);
    int b  = bg & 7;
    int mix= bg >> 3;
    int dst = ord[(mix*NB + b)*NG + j];
    cat[((size_t)(b*NG + dst))*(3*ND) + mix*ND + d] = in[idx];
}

// ---------------- LayerNorm (one warp per row), output tf32-rounded ----------------
__global__ void k_ln(const float* __restrict__ x, const float* __restrict__ wb,
                     const float* __restrict__ bbb, float* __restrict__ o,
                     int wmul, int wofs)
{
    int row  = blockIdx.x*8 + (threadIdx.x >> 5);
    int lane = threadIdx.x & 31;
    int mix  = row / ROWS;
    const float* w  = wb  + (size_t)(mix*wmul + wofs)*ND;
    const float* bb = bbb + (size_t)(mix*wmul + wofs)*ND;
    const float* xr = x + (size_t)row*ND;
    float s = 0.f, s2 = 0.f;
    #pragma unroll
    for (int d = lane; d < ND; d += 32) { float v = xr[d]; s += v; s2 += v*v; }
    #pragma unroll
    for (int off = 16; off; off >>= 1) {
        s  += __shfl_xor_sync(0xffffffffu, s,  off);
        s2 += __shfl_xor_sync(0xffffffffu, s2, off);
    }
    float m  = s * (1.f/ND);
    float var = s2 * (1.f/ND) - m*m;
    float rs = rsqrtf(var + 1e-5f);
    float* orow = o + (size_t)row*ND;
    #pragma unroll
    for (int d = lane; d < ND; d += 32)
        orow[d] = rnd_tf32((xr[d] - m)*rs*w[d] + bb[d]);
}

// ---------------- fused residual+flip then LayerNorm; lnout tf32-rounded ----------------
__global__ void k_resflip_ln(const float* __restrict__ hin, const float* __restrict__ mo,
                             const float* __restrict__ wb, const float* __restrict__ bbb,
                             float* __restrict__ hout, float* __restrict__ lnout,
                             int wmul, int wofs)
{
    int row  = blockIdx.x*8 + (threadIdx.x >> 5);  // 0..ROWS3-1
    int lane = threadIdx.x & 31;
    int bg = row / NG;
    int l  = row % NG;
    int mix = bg >> 3;
    const float* w  = wb  + (size_t)(mix*wmul + wofs)*ND;
    const float* bb = bbb + (size_t)(mix*wmul + wofs)*ND;
    size_t src = (size_t)(bg*NG + (NG-1-l))*ND;
    float v[ND/32];
    float s = 0.f, s2 = 0.f;
    #pragma unroll
    for (int t = 0; t < ND/32; t++) {
        int d = lane + 32*t;
        float x = hin[src + d] + mo[src + d];
        v[t] = x; s += x; s2 += x*x;
    }
    #pragma unroll
    for (int off = 16; off; off >>= 1) {
        s  += __shfl_xor_sync(0xffffffffu, s,  off);
        s2 += __shfl_xor_sync(0xffffffffu, s2, off);
    }
    float m  = s * (1.f/ND);
    float var = s2 * (1.f/ND) - m*m;
    float rs = rsqrtf(var + 1e-5f);
    float* ho = hout  + (size_t)row*ND;
    float* lo = lnout + (size_t)row*ND;
    #pragma unroll
    for (int t = 0; t < ND/32; t++) {
        int d = lane + 32*t;
        ho[d] = v[t];                                   // residual stream: full fp32
        lo[d] = rnd_tf32((v[t] - m)*rs*w[d] + bb[d]);   // GEMM A input: tf32
    }
}

#define GA_ST 36
#define G_STAGE128 ((128 + 128) * GA_ST)
#define G_SMEM_BYTES128 (3 * G_STAGE128 * 4)    // 110592 (3-stage)
#define G_STAGE64 ((64 + 64) * GA_ST)
#define G_SMEM_BYTES64 (2 * G_STAGE64 * 4)

// ---------------- tf32 GEMM BM=128, BN=128, BK=32; 3-stage pipeline; A,B pre-rounded ----------------
// epi: 0 none, 1 +bias, 2 +bias then exact GELU then tf32-round (for mid)
__global__ __launch_bounds__(256) void k_gemm_tc128(
    const float* __restrict__ A, const float* __restrict__ BwBase,
    float* __restrict__ C, int K, int ldc,
    const float* __restrict__ bias, int epi, size_t wstride, int blk)
{
    extern __shared__ float sm[];
    const int tid  = threadIdx.x;
    const int lane = tid & 31;
    const int warp = tid >> 5;
    const int wm   = warp & 1;     // 0..1 (64 rows each)
    const int wn   = warp >> 1;    // 0..3 (32 cols each)

    const int mix = (blockIdx.y * 128) / ROWS;
    const float* Bw = BwBase + (size_t)(mix*4 + blk) * wstride;

    const float* Ag = A  + (size_t)(blockIdx.y * 128) * K;
    const float* Bg = Bw + (size_t)(blockIdx.x * 128) * K;

    const int lr  = tid >> 3;        // 0..31
    const int lc4 = (tid & 7) * 4;   // float col of 16B chunk
    const int KT = K >> 5;

    float acc[4][4][4];
    #pragma unroll
    for (int mi = 0; mi < 4; mi++)
        #pragma unroll
        for (int ni = 0; ni < 4; ni++)
            #pragma unroll
            for (int q = 0; q < 4; q++) acc[mi][ni][q] = 0.f;

    auto load_stage = [&](int kt, int st) {
        float* as = sm + st * G_STAGE128;
        float* bs = as + 128 * GA_ST;
        int k0 = kt << 5;
        #pragma unroll
        for (int it = 0; it < 4; it++) {
            int r = lr + it * 32;
            cp_async16(&as[r * GA_ST + lc4], Ag + (size_t)r * K + k0 + lc4);
            cp_async16(&bs[r * GA_ST + lc4], Bg + (size_t)r * K + k0 + lc4);
        }
        asm volatile("cp.async.commit_group;\n" ::: "memory");
    };

    load_stage(0, 0);
    load_stage(1, 1);

    const int fr = lane >> 2;   // 0..7
    const int fc = lane & 3;    // 0..3

    for (int kt = 0; kt < KT; kt++) {
        if (kt + 1 < KT)
            asm volatile("cp.async.wait_group 1;\n" ::: "memory");
        else
            asm volatile("cp.async.wait_group 0;\n" ::: "memory");
        __syncthreads();

        // stage (kt+2)%3 was consumed at iteration kt-1; safe to refill now.
        if (kt + 2 < KT) load_stage(kt + 2, (kt + 2) % 3);

        const float* as = sm + (kt % 3) * G_STAGE128;
        const float* bs = as + 128 * GA_ST;

        #pragma unroll
        for (int ks = 0; ks < 4; ks++) {
            int k0 = ks << 3;
            uint32_t afr[4][4];
            uint32_t bfr[4][2];
            #pragma unroll
            for (int mi = 0; mi < 4; mi++) {
                const uint32_t* ap = (const uint32_t*)(as + (wm*64 + mi*16 + fr) * GA_ST + k0 + fc);
                afr[mi][0] = ap[0];
                afr[mi][1] = ap[8*GA_ST];
                afr[mi][2] = ap[4];
                afr[mi][3] = ap[8*GA_ST + 4];
            }
            #pragma unroll
            for (int ni = 0; ni < 4; ni++) {
                const uint32_t* bp = (const uint32_t*)(bs + (wn*32 + ni*8 + fr) * GA_ST + k0 + fc);
                bfr[ni][0] = bp[0];
                bfr[ni][1] = bp[4];
            }
            #pragma unroll
            for (int mi = 0; mi < 4; mi++)
                #pragma unroll
                for (int ni = 0; ni < 4; ni++) {
                    asm volatile(
                        "mma.sync.aligned.m16n8k8.row.col.f32.tf32.tf32.f32 "
                        "{%0,%1,%2,%3}, {%4,%5,%6,%7}, {%8,%9}, {%0,%1,%2,%3};\n"
                        : "+f"(acc[mi][ni][0]), "+f"(acc[mi][ni][1]),
                          "+f"(acc[mi][ni][2]), "+f"(acc[mi][ni][3])
                        : "r"(afr[mi][0]), "r"(afr[mi][1]),
                          "r"(afr[mi][2]), "r"(afr[mi][3]),
                          "r"(bfr[ni][0]), "r"(bfr[ni][1]));
                }
        }
        __syncthreads();
    }

    int row_base = blockIdx.y*128 + wm*64 + fr;
    int col_base = blockIdx.x*128 + wn*32 + fc*2;
    #pragma unroll
    for (int mi = 0; mi < 4; mi++) {
        #pragma unroll
        for (int ni = 0; ni < 4; ni++) {
            #pragma unroll
            for (int half = 0; half < 2; half++) {
                int row = row_base + mi*16 + half*8;
                int col = col_base + ni*8;
                float v0 = acc[mi][ni][half*2 + 0];
                float v1 = acc[mi][ni][half*2 + 1];
                if (epi >= 1) { v0 += bias[col]; v1 += bias[col+1]; }
                if (epi == 2) {
                    v0 = rnd_tf32(0.5f*v0*(1.f + erff(v0*0.70710678118654752f)));
                    v1 = rnd_tf32(0.5f*v1*(1.f + erff(v1*0.70710678118654752f)));
                }
                float2 vv = make_float2(v0, v1);
                *(float2*)(C + (size_t)row*ldc + col) = vv;
            }
        }
    }
}

// ---------------- tf32 GEMM (N=64, batched weights) for xproj (consumer CVT) ----------------
__global__ __launch_bounds__(256) void k_gemm_tc64(
    const float* __restrict__ A, const float* __restrict__ BwBase,
    float* __restrict__ C, int K, int ldc, int blk)
{
    extern __shared__ float sm[];
    const int tid  = threadIdx.x;
    const int lane = tid & 31;
    const int warp = tid >> 5;
    const int wm   = warp & 1;
    const int wn   = warp >> 1;   // 0..3, 16 cols each

    const int mix = (blockIdx.y * 64) / ROWS;
    const float* Bg = BwBase + (size_t)(mix*4 + blk) * (XRP*NDI);
    const float* Ag = A + (size_t)(blockIdx.y * 64) * K;

    const int lr  = tid >> 3;
    const int lc4 = (tid & 7) * 4;
    const int KT = K >> 5;

    float acc[2][2][4];
    #pragma unroll
    for (int mi = 0; mi < 2; mi++)
        #pragma unroll
        for (int ni = 0; ni < 2; ni++)
            #pragma unroll
            for (int q = 0; q < 4; q++) acc[mi][ni][q] = 0.f;

    auto load_stage = [&](int kt, int st) {
        float* as = sm + st * G_STAGE64;
        float* bs = as + 64 * GA_ST;
        int k0 = kt << 5;
        #pragma unroll
        for (int it = 0; it < 2; it++) {
            int r = lr + it * 32;
            cp_async16(&as[r * GA_ST + lc4], Ag + (size_t)r * K + k0 + lc4);
            cp_async16(&bs[r * GA_ST + lc4], Bg + (size_t)r * K + k0 + lc4);
        }
        asm volatile("cp.async.commit_group;\n" ::: "memory");
    };

    load_stage(0, 0);

    const int fr = lane >> 2;
    const int fc = lane & 3;

    for (int kt = 0; kt < KT; kt++) {
        if (kt + 1 < KT) load_stage(kt + 1, (kt + 1) & 1);
        if (kt + 1 < KT)
            asm volatile("cp.async.wait_group 1;\n" ::: "memory");
        else
            asm volatile("cp.async.wait_group 0;\n" ::: "memory");
        __syncthreads();

        const float* as = sm + (kt & 1) * G_STAGE64;
        const float* bs = as + 64 * GA_ST;

        #pragma unroll
        for (int ks = 0; ks < 4; ks++) {
            int k0 = ks << 3;
            uint32_t afr[2][4];
            uint32_t bfr[2][2];
            #pragma unroll
            for (int mi = 0; mi < 2; mi++) {
                const float* ap = as + (wm*32 + mi*16 + fr) * GA_ST + k0 + fc;
                afr[mi][0] = f2tf(ap[0]);
                afr[mi][1] = f2tf(ap[8*GA_ST]);
                afr[mi][2] = f2tf(ap[4]);
                afr[mi][3] = f2tf(ap[8*GA_ST + 4]);
            }
            #pragma unroll
            for (int ni = 0; ni < 2; ni++) {
                const float* bp = bs + (wn*16 + ni*8 + fr) * GA_ST + k0 + fc;
                bfr[ni][0] = f2tf(bp[0]);
                bfr[ni][1] = f2tf(bp[4]);
            }
            #pragma unroll
            for (int mi = 0; mi < 2; mi++)
                #pragma unroll
                for (int ni = 0; ni < 2; ni++) {
                    asm volatile(
                        "mma.sync.aligned.m16n8k8.row.col.f32.tf32.tf32.f32 "
                        "{%0,%1,%2,%3}, {%4,%5,%6,%7}, {%8,%9}, {%0,%1,%2,%3};\n"
                        : "+f"(acc[mi][ni][0]), "+f"(acc[mi][ni][1]),
                          "+f"(acc[mi][ni][2]), "+f"(acc[mi][ni][3])
                        : "r"(afr[mi][0]), "r"(afr[mi][1]),
                          "r"(afr[mi][2]), "r"(afr[mi][3]),
                          "r"(bfr[ni][0]), "r"(bfr[ni][1]));
                }
        }
        __syncthreads();
    }

    int row_base = blockIdx.y*64 + wm*32 + fr;
    int col_base = wn*16 + fc*2;
    #pragma unroll
    for (int mi = 0; mi < 2; mi++)
        #pragma unroll
        for (int ni = 0; ni < 2; ni++)
            #pragma unroll
            for (int half = 0; half < 2; half++) {
                int row = row_base + mi*16 + half*8;
                int col = col_base + ni*8;
                float2 vv = make_float2(acc[mi][ni][half*2], acc[mi][ni][half*2+1]);
                *(float2*)(C + (size_t)row*ldc + col) = vv;
            }
}

// ---------------- causal depthwise conv (K=4) + silu, 4 outputs per thread ----------------
__global__ void k_conv(const float* __restrict__ xz, const float* __restrict__ cw,
                       const float* __restrict__ cb, float* __restrict__ xc, int blk)
{
    int idx = blockIdx.x*256 + threadIdx.x;
    if (idx >= ROWS3*NDI/4) return;
    int c  = idx % NDI;
    int lt = (idx / NDI) % (NG/4);
    int bg = idx / (NDI*(NG/4));
    int l0 = lt*4;
    int i  = (bg >> 3)*4 + blk;
    const float* cwp = cw + (size_t)i*NDI*NKC + c*NKC;
    float w0 = cwp[0], w1 = cwp[1], w2 = cwp[2], w3 = cwp[3];
    float bias = cb[i*NDI + c];
    const float* xi = xz + (size_t)(bg*NG)*(2*NDI) + c;
    float t[7];
    #pragma unroll
    for (int k = 0; k < 7; k++) {
        int ll = l0 - 3 + k;
        t[k] = (ll >= 0) ? xi[(size_t)ll*(2*NDI)] : 0.f;
    }
    float* xo = xc + (size_t)(bg*NG + l0)*NDI + c;
    #pragma unroll
    for (int q = 0; q < 4; q++) {
        float acc = bias + w0*t[q] + w1*t[q+1] + w2*t[q+2] + w3*t[q+3];
        float sig = 1.f/(1.f + __expf(-acc));
        xo[(size_t)q*NDI] = acc*sig;
    }
}

// ---------------- dt = softplus(xd[:, :24] @ dw^T + db) (batched) ----------------
__global__ void k_dt(const float* __restrict__ xd, const float* __restrict__ dw,
                     const float* __restrict__ db, float* __restrict__ dtb, int blk)
{
    int idx = blockIdx.x*256 + threadIdx.x;
    if (idx >= ROWS3*NDI) return;
    int c   = idx % NDI;
    int row = idx / NDI;
    int i   = (row / ROWS)*4 + blk;
    const float* xr = xd + (size_t)row*XRP;
    const float* wr = dw + (size_t)i*NDI*NR + c*NR;
    float acc = db[i*NDI + c];
    #pragma unroll
    for (int r = 0; r < NR; r++) acc += xr[r]*wr[r];
    dtb[idx] = (acc > 20.f) ? acc : log1pf(__expf(acc));
}

// ---------------- selective scan: 8 lanes/channel x 2 states/lane ----------------
__global__ __launch_bounds__(512) void k_scan(
    const float* __restrict__ dtb, const float* __restrict__ xc,
    const float* __restrict__ xd, const float* __restrict__ alogB,
    float* __restrict__ y, int blk)
{
    int mix  = blockIdx.z;
    int b    = blockIdx.y;
    int i    = mix*4 + blk;
    int tid  = threadIdx.x;
    int lane = tid & 31;
    int j    = lane & 7;           // lane within channel group
    int ch   = tid >> 3;           // 0..63
    int c    = blockIdx.x*64 + ch;
    const float* alog = alogB + (size_t)i*NDI*NS + (size_t)c*NS;
    float Av0 = -__expf(alog[2*j]);
    float Av1 = -__expf(alog[2*j+1]);
    size_t rowbase = (size_t)(mix*ROWS + b*NG);
    const float* dtp = dtb + rowbase*NDI + c;
    const float* xcp = xc  + rowbase*NDI + c;
    const float* xr  = xd  + rowbase*XRP + 24 + 4*j;
    float*       yp  = y   + rowbase*NDI + c;
    float h0 = 0.f, h1 = 0.f;
    for (int l = 0; l < NG; ++l) {
        float dt_v = dtp[(size_t)l*NDI];
        float xc_v = xcp[(size_t)l*NDI];
        float4 bc  = *(const float4*)(xr + (size_t)l*XRP);   // B_{2j},C_{2j},B_{2j+1},C_{2j+1}
        float a0 = __expf(dt_v*Av0);
        float a1 = __expf(dt_v*Av1);
        float dx = dt_v*xc_v;
        h0 = a0*h0 + dx*bc.x;
        h1 = a1*h1 + dx*bc.z;
        float p = h0*bc.y + h1*bc.w;
        p += __shfl_xor_sync(0xffffffffu, p, 1);
        p += __shfl_xor_sync(0xffffffffu, p, 2);
        p += __shfl_xor_sync(0xffffffffu, p, 4);
        if (j == 0) yp[(size_t)l*NDI] = p;
    }
}

// ---------------- gate: y = (y + xc*Dp) * silu(z), output tf32-rounded ----------------
__global__ void k_gate(float* __restrict__ y, const float* __restrict__ xc,
                       const float* __restrict__ DpB, const float* __restrict__ xz, int blk)
{
    int idx = blockIdx.x*256 + threadIdx.x;
    if (idx >= ROWS3*NDI) return;
    int c   = idx % NDI;
    int row = idx / NDI;
    int i   = (row / ROWS)*4 + blk;
    float z = xz[(size_t)row*(2*NDI) + NDI + c];
    float sig = 1.f/(1.f + __expf(-z));
    y[idx] = rnd_tf32((y[idx] + xc[idx]*DpB[i*NDI + c]) * (z*sig));
}

// ---------------- host orchestration ----------------
extern "C" void kernel_launch(void* const* d_in, const int* in_sizes, int n_in,
                              void* d_out, int out_size)
{
    const float* center    = (const float*)d_in[0];
    const float* ginput    = (const float*)d_in[1];
    const float* norm_w    = (const float*)d_in[2];
    const float* norm_b    = (const float*)d_in[3];
    const float* inproj_w  = (const float*)d_in[4];
    const float* conv_w    = (const float*)d_in[5];
    const float* conv_b    = (const float*)d_in[6];
    const float* xproj_w   = (const float*)d_in[7];
    const float* dtproj_w  = (const float*)d_in[8];
    const float* dtproj_b  = (const float*)d_in[9];
    const float* A_log     = (const float*)d_in[10];
    const float* Dp        = (const float*)d_in[11];
    const float* outproj_w = (const float*)d_in[12];
    const float* normf_w   = (const float*)d_in[13];
    const float* normf_b   = (const float*)d_in[14];
    const float* dw1       = (const float*)d_in[15];
    const float* db1       = (const float*)d_in[16];
    const float* dw2       = (const float*)d_in[17];
    const float* db2       = (const float*)d_in[18];
    float* out = (float*)d_out;

    float *h, *h2, *ln, *xz, *xc, *xd, *dtb, *y, *mo, *cat, *mid, *xwp;
    float *wip, *wop, *w1c, *w2c; int* ord;
    cudaGetSymbolAddress((void**)&h,   g_h);
    cudaGetSymbolAddress((void**)&h2,  g_h2);
    cudaGetSymbolAddress((void**)&ln,  g_ln);
    cudaGetSymbolAddress((void**)&xz,  g_xz);
    cudaGetSymbolAddress((void**)&xc,  g_xc);
    cudaGetSymbolAddress((void**)&xd,  g_xd);
    cudaGetSymbolAddress((void**)&dtb, g_dt);
    cudaGetSymbolAddress((void**)&y,   g_y);
    cudaGetSymbolAddress((void**)&mo,  g_mo);
    cudaGetSymbolAddress((void**)&cat, g_cat);
    cudaGetSymbolAddress((void**)&mid, g_mid);
    cudaGetSymbolAddress((void**)&xwp, g_xwp);
    cudaGetSymbolAddress((void**)&wip, g_wip);
    cudaGetSymbolAddress((void**)&wop, g_wop);
    cudaGetSymbolAddress((void**)&w1c, g_w1c);
    cudaGetSymbolAddress((void**)&w2c, g_w2c);
    cudaGetSymbolAddress((void**)&ord, g_ord);

    cudaFuncSetAttribute(k_gemm_tc128, cudaFuncAttributeMaxDynamicSharedMemorySize, G_SMEM_BYTES128);
    cudaFuncSetAttribute(k_gemm_tc64,  cudaFuncAttributeMaxDynamicSharedMemorySize, G_SMEM_BYTES64);

    const int EB3  = (ROWS3*ND  + 255)/256;
    const int EDI3 = (ROWS3*NDI + 255)/256;
    const int EC4  = (ROWS3*NDI/4 + 255)/256;

    // one-time per launch: weight conversions + padding
    k_cvt_all<<<(N_CVT + 255)/256, 256>>>(inproj_w, wip, outproj_w, wop, dw1, w1c, dw2, w2c);
    k_padxw<<<(12*XRP*NDI + 255)/256, 256>>>(xproj_w, xwp);

    k_argsort<<<dim3(NB,3), 256>>>(center, ord);
    k_gather<<<EB3,256>>>(ginput, ord, h);
    k_ln<<<ROWS3/8,256>>>(h, norm_w, norm_b, ln, 4, 0);

    for (int blk = 0; blk < 4; blk++) {
        float* hin  = (blk & 1) ? h2 : h;
        float* hout = (blk & 1) ? h  : h2;

        k_gemm_tc128<<<dim3(2*NDI/128, ROWS3/128),256,G_SMEM_BYTES128>>>(
            ln, wip, xz, ND, 2*NDI, nullptr, 0, (size_t)2*NDI*ND, blk);

        k_conv<<<EC4,256>>>(xz, conv_w, conv_b, xc, blk);

        k_gemm_tc64<<<dim3(1, ROWS3/64),256,G_SMEM_BYTES64>>>(
            xc, xwp, xd, NDI, XRP, blk);

        k_dt<<<EDI3,256>>>(xd, dtproj_w, dtproj_b, dtb, blk);

        k_scan<<<dim3(NDI/64, NB, 3),512>>>(dtb, xc, xd, A_log, y, blk);

        k_gate<<<EDI3,256>>>(y, xc, Dp, xz, blk);

        k_gemm_tc128<<<dim3(ND/128, ROWS3/128),256,G_SMEM_BYTES128>>>(
            y, wop, mo, NDI, ND, nullptr, 0, (size_t)ND*NDI, blk);

        if (blk < 3)
            k_resflip_ln<<<ROWS3/8,256>>>(hin, mo, norm_w, norm_b, hout, ln, 4, blk+1);
        else
            k_resflip_ln<<<ROWS3/8,256>>>(hin, mo, normf_w, normf_b, hout, ln, 1, 0);
    }

    k_scatter<<<EB3,256>>>(ln, ord, cat);

    // final MLP (M=4096 rows; mix evaluates to 0 within row range, wstride=0 -> weight offset 0)
    k_gemm_tc128<<<dim3(ND/128, ROWS/128),256,G_SMEM_BYTES128>>>(cat, w1c, mid, 3*ND, ND, db1, 2, 0, 0);
    k_gemm_tc128<<<dim3(ND/128, ROWS/128),256,G_SMEM_BYTES128>>>(mid, w2c, out, ND,   ND, db2, 1, 0, 0);
}

// round 17
// speedup vs baseline: 1.4583x; 1.4583x over previous
#include <cuda_runtime.h>
#include <cstdint>
#include <cstddef>
#include <math.h>

#define NB 8
#define NG 512
#define ND 384
#define NDI 768
#define NS 16
#define NR 24
#define NKC 4
#define ROWS (NB*NG)          // 4096
#define ROWS3 (3*ROWS)        // 12288
#define XRP 64                // padded xd width (real width 56)

// ---------------- scratch (device globals: no allocation allowed) ----------------
__device__ float g_h  [ROWS3*ND];
__device__ float g_h2 [ROWS3*ND];
__device__ float g_ln [ROWS3*ND];
__device__ float g_xz [ROWS3*2*NDI];
__device__ float g_xc [ROWS3*NDI];
__device__ float g_xd [ROWS3*XRP];
__device__ float g_dt [ROWS3*NDI];
__device__ float g_y  [ROWS3*NDI];
__device__ float g_mo [ROWS3*ND];
__device__ float g_cat[ROWS*3*ND];
__device__ float g_mid[ROWS*ND];
__device__ float g_xwp[12*XRP*NDI];       // zero-padded xproj weights (B/C interleaved)
__device__ float g_wip[12*2*NDI*ND];      // tf32-rounded inproj weights
__device__ float g_wop[12*ND*NDI];        // tf32-rounded outproj weights
__device__ float g_w1c[ND*3*ND];          // tf32-rounded MLP w1
__device__ float g_w2c[ND*ND];            // tf32-rounded MLP w2
__device__ float g_dwp[12*NDI*32 + 256];  // dt weights padded K=24->32 (rows 24..31 zero), tf32
__device__ int   g_ord[3*NB*NG];

// ---------------- tf32 helpers ----------------
__device__ __forceinline__ void cp_async16(float* dst, const float* src)
{
    uint32_t d = (uint32_t)__cvta_generic_to_shared(dst);
    asm volatile("cp.async.cg.shared.global [%0], [%1], 16;\n" :: "r"(d), "l"(src));
}
__device__ __forceinline__ uint32_t f2tf(float f)
{
    uint32_t u;
    asm("cvt.rna.tf32.f32 %0, %1;\n" : "=r"(u) : "f"(f));
    return u;
}
__device__ __forceinline__ float rnd_tf32(float f)
{
    return __uint_as_float(f2tf(f));
}

// ---------------- merged tf32 weight conversion (4 arrays, one launch) ----------------
#define N_WIP (12*2*NDI*ND)
#define N_WOP (12*ND*NDI)
#define N_W1  (ND*3*ND)
#define N_W2  (ND*ND)
#define N_CVT (N_WIP + N_WOP + N_W1 + N_W2)

__global__ void k_cvt_all(const float* __restrict__ a0, float* __restrict__ o0,
                          const float* __restrict__ a1, float* __restrict__ o1,
                          const float* __restrict__ a2, float* __restrict__ o2,
                          const float* __restrict__ a3, float* __restrict__ o3)
{
    int idx = blockIdx.x*256 + threadIdx.x;
    if (idx >= N_CVT) return;
    if (idx < N_WIP)                       { o0[idx] = rnd_tf32(a0[idx]); return; }
    idx -= N_WIP;
    if (idx < N_WOP)                       { o1[idx] = rnd_tf32(a1[idx]); return; }
    idx -= N_WOP;
    if (idx < N_W1)                        { o2[idx] = rnd_tf32(a2[idx]); return; }
    idx -= N_W1;
    o3[idx] = rnd_tf32(a3[idx]);
}

// ---------------- pad dt weights: [12][768][24] -> [12][768][32], cols 24..31 zero ----------------
__global__ void k_paddw(const float* __restrict__ dw, float* __restrict__ dwp)
{
    int idx = blockIdx.x*256 + threadIdx.x;
    if (idx >= 12*NDI*32) return;
    int kk = idx & 31;
    int c  = (idx >> 5) % NDI;
    int i  = idx / (32*NDI);
    dwp[idx] = (kk < NR) ? rnd_tf32(dw[((size_t)i*NDI + c)*NR + kk]) : 0.f;
}

// ---------------- argsort (bitonic, 512 keys per (b, mix)) ----------------
__global__ void k_argsort(const float* __restrict__ center, int* __restrict__ ord)
{
    __shared__ float key[NG];
    __shared__ int   idx[NG];
    int b   = blockIdx.x;
    int mix = blockIdx.y;          // mix 0 -> axis 2 (z), 1 -> 1 (y), 2 -> 0 (x)
    int axis = 2 - mix;
    int tid = threadIdx.x;         // 256
    for (int g = tid; g < NG; g += 256) {
        key[g] = center[(b*NG + g)*3 + axis];
        idx[g] = g;
    }
    __syncthreads();
    for (int k = 2; k <= NG; k <<= 1) {
        for (int j = k >> 1; j > 0; j >>= 1) {
            for (int t = tid; t < NG; t += 256) {
                int p = t ^ j;
                if (p > t) {
                    bool up = ((t & k) == 0);
                    float a = key[t], c = key[p];
                    bool sw = up ? (a > c) : (a < c);
                    if (sw) {
                        key[t] = c; key[p] = a;
                        int ia = idx[t]; idx[t] = idx[p]; idx[p] = ia;
                    }
                }
            }
            __syncthreads();
        }
    }
    for (int g = tid; g < NG; g += 256)
        ord[(mix*NB + b)*NG + g] = idx[g];
}

// ---------------- pad + permute xproj weights: [12][56][768] -> [12][64][768] ----------------
// Output column order: 0..23 = dt rows; 24+2s = B_s, 24+2s+1 = C_s; 56..63 zero pad.
__global__ void k_padxw(const float* __restrict__ xw, float* __restrict__ xwp)
{
    int idx = blockIdx.x*256 + threadIdx.x;
    if (idx >= 12*XRP*NDI) return;
    int k = idx % NDI;
    int n = (idx / NDI) % XRP;
    int i = idx / (NDI*XRP);
    int src_n;
    if (n < 24)      src_n = n;
    else if (n < 56) { int q = n - 24; src_n = 24 + (q & 1)*16 + (q >> 1); }
    else             src_n = -1;
    xwp[idx] = (src_n >= 0) ? xw[((size_t)i*56 + src_n)*NDI + k] : 0.f;
}

// ---------------- gather (all 3 mixers) ----------------
__global__ void k_gather(const float* __restrict__ in, const int* __restrict__ ord,
                         float* __restrict__ out)
{
    int idx = blockIdx.x*256 + threadIdx.x;
    if (idx >= ROWS3*ND) return;
    int d  = idx % ND;
    int j  = (idx / ND) % NG;
    int bg = idx / (ND*NG);      // 0..23
    int b  = bg & 7;
    int mix= bg >> 3;
    int src = ord[(mix*NB + b)*NG + j];
    out[idx] = in[((size_t)(b*NG + src))*ND + d];
}

// ---------------- scatter into concat buffer ----------------
__global__ void k_scatter(const float* __restrict__ in, const int* __restrict__ ord,
                          float* __restrict__ cat)
{
    int idx = blockIdx.x*256 + threadIdx.x;
    if (idx >= ROWS3*ND) return;
    int d  = idx % ND;
    int j  = (idx / ND) % NG;
    int bg = idx / (ND*NG);
    int b  = bg & 7;
    int mix= bg >> 3;
    int dst = ord[(mix*NB + b)*NG + j];
    cat[((size_t)(b*NG + dst))*(3*ND) + mix*ND + d] = in[idx];
}

// ---------------- LayerNorm (one warp per row), output tf32-rounded ----------------
__global__ void k_ln(const float* __restrict__ x, const float* __restrict__ wb,
                     const float* __restrict__ bbb, float* __restrict__ o,
                     int wmul, int wofs)
{
    int row  = blockIdx.x*8 + (threadIdx.x >> 5);
    int lane = threadIdx.x & 31;
    int mix  = row / ROWS;
    const float* w  = wb  + (size_t)(mix*wmul + wofs)*ND;
    const float* bb = bbb + (size_t)(mix*wmul + wofs)*ND;
    const float* xr = x + (size_t)row*ND;
    float s = 0.f, s2 = 0.f;
    #pragma unroll
    for (int d = lane; d < ND; d += 32) { float v = xr[d]; s += v; s2 += v*v; }
    #pragma unroll
    for (int off = 16; off; off >>= 1) {
        s  += __shfl_xor_sync(0xffffffffu, s,  off);
        s2 += __shfl_xor_sync(0xffffffffu, s2, off);
    }
    float m  = s * (1.f/ND);
    float var = s2 * (1.f/ND) - m*m;
    float rs = rsqrtf(var + 1e-5f);
    float* orow = o + (size_t)row*ND;
    #pragma unroll
    for (int d = lane; d < ND; d += 32)
        orow[d] = rnd_tf32((xr[d] - m)*rs*w[d] + bb[d]);
}

// ---------------- fused residual+flip then LayerNorm; lnout tf32-rounded ----------------
__global__ void k_resflip_ln(const float* __restrict__ hin, const float* __restrict__ mo,
                             const float* __restrict__ wb, const float* __restrict__ bbb,
                             float* __restrict__ hout, float* __restrict__ lnout,
                             int wmul, int wofs)
{
    int row  = blockIdx.x*8 + (threadIdx.x >> 5);  // 0..ROWS3-1
    int lane = threadIdx.x & 31;
    int bg = row / NG;
    int l  = row % NG;
    int mix = bg >> 3;
    const float* w  = wb  + (size_t)(mix*wmul + wofs)*ND;
    const float* bb = bbb + (size_t)(mix*wmul + wofs)*ND;
    size_t src = (size_t)(bg*NG + (NG-1-l))*ND;
    float v[ND/32];
    float s = 0.f, s2 = 0.f;
    #pragma unroll
    for (int t = 0; t < ND/32; t++) {
        int d = lane + 32*t;
        float x = hin[src + d] + mo[src + d];
        v[t] = x; s += x; s2 += x*x;
    }
    #pragma unroll
    for (int off = 16; off; off >>= 1) {
        s  += __shfl_xor_sync(0xffffffffu, s,  off);
        s2 += __shfl_xor_sync(0xffffffffu, s2, off);
    }
    float m  = s * (1.f/ND);
    float var = s2 * (1.f/ND) - m*m;
    float rs = rsqrtf(var + 1e-5f);
    float* ho = hout  + (size_t)row*ND;
    float* lo = lnout + (size_t)row*ND;
    #pragma unroll
    for (int t = 0; t < ND/32; t++) {
        int d = lane + 32*t;
        ho[d] = v[t];                                   // residual stream: full fp32
        lo[d] = rnd_tf32((v[t] - m)*rs*w[d] + bb[d]);   // GEMM A input: tf32
    }
}

#define GA_ST 36
#define G_STAGE128 ((128 + 128) * GA_ST)
#define G_SMEM_BYTES128 (2 * G_STAGE128 * 4)    // 73728 (2-stage)
#define G_STAGE64 ((64 + 64) * GA_ST)
#define G_SMEM_BYTES64 (2 * G_STAGE64 * 4)

// ---------------- tf32 GEMM BM=128, BN=128, BK=32; A,B pre-rounded (no CVT) ----------------
// A row stride lda (>=K); weights row stride K.
// epi: 0 none, 1 +bias, 2 +bias,GELU,tf32-round, 3 +bias,softplus
__global__ __launch_bounds__(256) void k_gemm_tc128(
    const float* __restrict__ A, const float* __restrict__ BwBase,
    float* __restrict__ C, int K, int lda, int ldc,
    const float* __restrict__ bias, size_t bstride, int epi, size_t wstride, int blk)
{
    extern __shared__ float sm[];
    const int tid  = threadIdx.x;
    const int lane = tid & 31;
    const int warp = tid >> 5;
    const int wm   = warp & 1;     // 0..1 (64 rows each)
    const int wn   = warp >> 1;    // 0..3 (32 cols each)

    const int mix = (blockIdx.y * 128) / ROWS;
    const float* Bw = BwBase + (size_t)(mix*4 + blk) * wstride;
    const float* bp = bias ? (bias + (size_t)(mix*4 + blk) * bstride) : bias;

    const float* Ag = A  + (size_t)(blockIdx.y * 128) * lda;
    const float* Bg = Bw + (size_t)(blockIdx.x * 128) * K;

    const int lr  = tid >> 3;        // 0..31
    const int lc4 = (tid & 7) * 4;   // float col of 16B chunk
    const int KT = K >> 5;

    float acc[4][4][4];
    #pragma unroll
    for (int mi = 0; mi < 4; mi++)
        #pragma unroll
        for (int ni = 0; ni < 4; ni++)
            #pragma unroll
            for (int q = 0; q < 4; q++) acc[mi][ni][q] = 0.f;

    auto load_stage = [&](int kt, int st) {
        float* as = sm + st * G_STAGE128;
        float* bs = as + 128 * GA_ST;
        int k0 = kt << 5;
        #pragma unroll
        for (int it = 0; it < 4; it++) {
            int r = lr + it * 32;
            cp_async16(&as[r * GA_ST + lc4], Ag + (size_t)r * lda + k0 + lc4);
            cp_async16(&bs[r * GA_ST + lc4], Bg + (size_t)r * K   + k0 + lc4);
        }
        asm volatile("cp.async.commit_group;\n" ::: "memory");
    };

    load_stage(0, 0);

    const int fr = lane >> 2;   // 0..7
    const int fc = lane & 3;    // 0..3

    for (int kt = 0; kt < KT; kt++) {
        if (kt + 1 < KT) load_stage(kt + 1, (kt + 1) & 1);
        if (kt + 1 < KT)
            asm volatile("cp.async.wait_group 1;\n" ::: "memory");
        else
            asm volatile("cp.async.wait_group 0;\n" ::: "memory");
        __syncthreads();

        const float* as = sm + (kt & 1) * G_STAGE128;
        const float* bs = as + 128 * GA_ST;

        #pragma unroll
        for (int ks = 0; ks < 4; ks++) {
            int k0 = ks << 3;
            uint32_t afr[4][4];
            uint32_t bfr[4][2];
            #pragma unroll
            for (int mi = 0; mi < 4; mi++) {
                const uint32_t* ap = (const uint32_t*)(as + (wm*64 + mi*16 + fr) * GA_ST + k0 + fc);
                afr[mi][0] = ap[0];
                afr[mi][1] = ap[8*GA_ST];
                afr[mi][2] = ap[4];
                afr[mi][3] = ap[8*GA_ST + 4];
            }
            #pragma unroll
            for (int ni = 0; ni < 4; ni++) {
                const uint32_t* bp2 = (const uint32_t*)(bs + (wn*32 + ni*8 + fr) * GA_ST + k0 + fc);
                bfr[ni][0] = bp2[0];
                bfr[ni][1] = bp2[4];
            }
            #pragma unroll
            for (int mi = 0; mi < 4; mi++)
                #pragma unroll
                for (int ni = 0; ni < 4; ni++) {
                    asm volatile(
                        "mma.sync.aligned.m16n8k8.row.col.f32.tf32.tf32.f32 "
                        "{%0,%1,%2,%3}, {%4,%5,%6,%7}, {%8,%9}, {%0,%1,%2,%3};\n"
                        : "+f"(acc[mi][ni][0]), "+f"(acc[mi][ni][1]),
                          "+f"(acc[mi][ni][2]), "+f"(acc[mi][ni][3])
                        : "r"(afr[mi][0]), "r"(afr[mi][1]),
                          "r"(afr[mi][2]), "r"(afr[mi][3]),
                          "r"(bfr[ni][0]), "r"(bfr[ni][1]));
                }
        }
        __syncthreads();
    }

    int row_base = blockIdx.y*128 + wm*64 + fr;
    int col_base = blockIdx.x*128 + wn*32 + fc*2;
    #pragma unroll
    for (int mi = 0; mi < 4; mi++) {
        #pragma unroll
        for (int ni = 0; ni < 4; ni++) {
            #pragma unroll
            for (int half = 0; half < 2; half++) {
                int row = row_base + mi*16 + half*8;
                int col = col_base + ni*8;
                float v0 = acc[mi][ni][half*2 + 0];
                float v1 = acc[mi][ni][half*2 + 1];
                if (epi >= 1) { v0 += bp[col]; v1 += bp[col+1]; }
                if (epi == 2) {
                    v0 = rnd_tf32(0.5f*v0*(1.f + erff(v0*0.70710678118654752f)));
                    v1 = rnd_tf32(0.5f*v1*(1.f + erff(v1*0.70710678118654752f)));
                } else if (epi == 3) {
                    v0 = (v0 > 20.f) ? v0 : log1pf(__expf(v0));
                    v1 = (v1 > 20.f) ? v1 : log1pf(__expf(v1));
                }
                float2 vv = make_float2(v0, v1);
                *(float2*)(C + (size_t)row*ldc + col) = vv;
            }
        }
    }
}

// ---------------- tf32 GEMM (N=64, batched weights) for xproj (consumer CVT) ----------------
__global__ __launch_bounds__(256) void k_gemm_tc64(
    const float* __restrict__ A, const float* __restrict__ BwBase,
    float* __restrict__ C, int K, int ldc, int blk)
{
    extern __shared__ float sm[];
    const int tid  = threadIdx.x;
    const int lane = tid & 31;
    const int warp = tid >> 5;
    const int wm   = warp & 1;
    const int wn   = warp >> 1;   // 0..3, 16 cols each

    const int mix = (blockIdx.y * 64) / ROWS;
    const float* Bg = BwBase + (size_t)(mix*4 + blk) * (XRP*NDI);
    const float* Ag = A + (size_t)(blockIdx.y * 64) * K;

    const int lr  = tid >> 3;
    const int lc4 = (tid & 7) * 4;
    const int KT = K >> 5;

    float acc[2][2][4];
    #pragma unroll
    for (int mi = 0; mi < 2; mi++)
        #pragma unroll
        for (int ni = 0; ni < 2; ni++)
            #pragma unroll
            for (int q = 0; q < 4; q++) acc[mi][ni][q] = 0.f;

    auto load_stage = [&](int kt, int st) {
        float* as = sm + st * G_STAGE64;
        float* bs = as + 64 * GA_ST;
        int k0 = kt << 5;
        #pragma unroll
        for (int it = 0; it < 2; it++) {
            int r = lr + it * 32;
            cp_async16(&as[r * GA_ST + lc4], Ag + (size_t)r * K + k0 + lc4);
            cp_async16(&bs[r * GA_ST + lc4], Bg + (size_t)r * K + k0 + lc4);
        }
        asm volatile("cp.async.commit_group;\n" ::: "memory");
    };

    load_stage(0, 0);

    const int fr = lane >> 2;
    const int fc = lane & 3;

    for (int kt = 0; kt < KT; kt++) {
        if (kt + 1 < KT) load_stage(kt + 1, (kt + 1) & 1);
        if (kt + 1 < KT)
            asm volatile("cp.async.wait_group 1;\n" ::: "memory");
        else
            asm volatile("cp.async.wait_group 0;\n" ::: "memory");
        __syncthreads();

        const float* as = sm + (kt & 1) * G_STAGE64;
        const float* bs = as + 64 * GA_ST;

        #pragma unroll
        for (int ks = 0; ks < 4; ks++) {
            int k0 = ks << 3;
            uint32_t afr[2][4];
            uint32_t bfr[2][2];
            #pragma unroll
            for (int mi = 0; mi < 2; mi++) {
                const float* ap = as + (wm*32 + mi*16 + fr) * GA_ST + k0 + fc;
                afr[mi][0] = f2tf(ap[0]);
                afr[mi][1] = f2tf(ap[8*GA_ST]);
                afr[mi][2] = f2tf(ap[4]);
                afr[mi][3] = f2tf(ap[8*GA_ST + 4]);
            }
            #pragma unroll
            for (int ni = 0; ni < 2; ni++) {
                const float* bp = bs + (wn*16 + ni*8 + fr) * GA_ST + k0 + fc;
                bfr[ni][0] = f2tf(bp[0]);
                bfr[ni][1] = f2tf(bp[4]);
            }
            #pragma unroll
            for (int mi = 0; mi < 2; mi++)
                #pragma unroll
                for (int ni = 0; ni < 2; ni++) {
                    asm volatile(
                        "mma.sync.aligned.m16n8k8.row.col.f32.tf32.tf32.f32 "
                        "{%0,%1,%2,%3}, {%4,%5,%6,%7}, {%8,%9}, {%0,%1,%2,%3};\n"
                        : "+f"(acc[mi][ni][0]), "+f"(acc[mi][ni][1]),
                          "+f"(acc[mi][ni][2]), "+f"(acc[mi][ni][3])
                        : "r"(afr[mi][0]), "r"(afr[mi][1]),
                          "r"(afr[mi][2]), "r"(afr[mi][3]),
                          "r"(bfr[ni][0]), "r"(bfr[ni][1]));
                }
        }
        __syncthreads();
    }

    int row_base = blockIdx.y*64 + wm*32 + fr;
    int col_base = wn*16 + fc*2;
    #pragma unroll
    for (int mi = 0; mi < 2; mi++)
        #pragma unroll
        for (int ni = 0; ni < 2; ni++)
            #pragma unroll
            for (int half = 0; half < 2; half++) {
                int row = row_base + mi*16 + half*8;
                int col = col_base + ni*8;
                float2 vv = make_float2(acc[mi][ni][half*2], acc[mi][ni][half*2+1]);
                *(float2*)(C + (size_t)row*ldc + col) = vv;
            }
}

// ---------------- causal depthwise conv (K=4) + silu, 4 outputs per thread ----------------
__global__ void k_conv(const float* __restrict__ xz, const float* __restrict__ cw,
                       const float* __restrict__ cb, float* __restrict__ xc, int blk)
{
    int idx = blockIdx.x*256 + threadIdx.x;
    if (idx >= ROWS3*NDI/4) return;
    int c  = idx % NDI;
    int lt = (idx / NDI) % (NG/4);
    int bg = idx / (NDI*(NG/4));
    int l0 = lt*4;
    int i  = (bg >> 3)*4 + blk;
    const float* cwp = cw + (size_t)i*NDI*NKC + c*NKC;
    float w0 = cwp[0], w1 = cwp[1], w2 = cwp[2], w3 = cwp[3];
    float bias = cb[i*NDI + c];
    const float* xi = xz + (size_t)(bg*NG)*(2*NDI) + c;
    float t[7];
    #pragma unroll
    for (int k = 0; k < 7; k++) {
        int ll = l0 - 3 + k;
        t[k] = (ll >= 0) ? xi[(size_t)ll*(2*NDI)] : 0.f;
    }
    float* xo = xc + (size_t)(bg*NG + l0)*NDI + c;
    #pragma unroll
    for (int q = 0; q < 4; q++) {
        float acc = bias + w0*t[q] + w1*t[q+1] + w2*t[q+2] + w3*t[q+3];
        float sig = 1.f/(1.f + __expf(-acc));
        xo[(size_t)q*NDI] = acc*sig;
    }
}

// ---------------- selective scan: 8 lanes/channel x 2 states/lane ----------------
__global__ __launch_bounds__(512) void k_scan(
    const float* __restrict__ dtb, const float* __restrict__ xc,
    const float* __restrict__ xd, const float* __restrict__ alogB,
    float* __restrict__ y, int blk)
{
    int mix  = blockIdx.z;
    int b    = blockIdx.y;
    int i    = mix*4 + blk;
    int tid  = threadIdx.x;
    int lane = tid & 31;
    int j    = lane & 7;           // lane within channel group
    int ch   = tid >> 3;           // 0..63
    int c    = blockIdx.x*64 + ch;
    const float* alog = alogB + (size_t)i*NDI*NS + (size_t)c*NS;
    float Av0 = -__expf(alog[2*j]);
    float Av1 = -__expf(alog[2*j+1]);
    size_t rowbase = (size_t)(mix*ROWS + b*NG);
    const float* dtp = dtb + rowbase*NDI + c;
    const float* xcp = xc  + rowbase*NDI + c;
    const float* xr  = xd  + rowbase*XRP + 24 + 4*j;
    float*       yp  = y   + rowbase*NDI + c;
    float h0 = 0.f, h1 = 0.f;
    for (int l = 0; l < NG; ++l) {
        float dt_v = dtp[(size_t)l*NDI];
        float xc_v = xcp[(size_t)l*NDI];
        float4 bc  = *(const float4*)(xr + (size_t)l*XRP);   // B_{2j},C_{2j},B_{2j+1},C_{2j+1}
        float a0 = __expf(dt_v*Av0);
        float a1 = __expf(dt_v*Av1);
        float dx = dt_v*xc_v;
        h0 = a0*h0 + dx*bc.x;
        h1 = a1*h1 + dx*bc.z;
        float p = h0*bc.y + h1*bc.w;
        p += __shfl_xor_sync(0xffffffffu, p, 1);
        p += __shfl_xor_sync(0xffffffffu, p, 2);
        p += __shfl_xor_sync(0xffffffffu, p, 4);
        if (j == 0) yp[(size_t)l*NDI] = p;
    }
}

// ---------------- gate: y = (y + xc*Dp) * silu(z), output tf32-rounded ----------------
__global__ void k_gate(float* __restrict__ y, const float* __restrict__ xc,
                       const float* __restrict__ DpB, const float* __restrict__ xz, int blk)
{
    int idx = blockIdx.x*256 + threadIdx.x;
    if (idx >= ROWS3*NDI) return;
    int c   = idx % NDI;
    int row = idx / NDI;
    int i   = (row / ROWS)*4 + blk;
    float z = xz[(size_t)row*(2*NDI) + NDI + c];
    float sig = 1.f/(1.f + __expf(-z));
    y[idx] = rnd_tf32((y[idx] + xc[idx]*DpB[i*NDI + c]) * (z*sig));
}

// ---------------- host orchestration ----------------
extern "C" void kernel_launch(void* const* d_in, const int* in_sizes, int n_in,
                              void* d_out, int out_size)
{
    const float* center    = (const float*)d_in[0];
    const float* ginput    = (const float*)d_in[1];
    const float* norm_w    = (const float*)d_in[2];
    const float* norm_b    = (const float*)d_in[3];
    const float* inproj_w  = (const float*)d_in[4];
    const float* conv_w    = (const float*)d_in[5];
    const float* conv_b    = (const float*)d_in[6];
    const float* xproj_w   = (const float*)d_in[7];
    const float* dtproj_w  = (const float*)d_in[8];
    const float* dtproj_b  = (const float*)d_in[9];
    const float* A_log     = (const float*)d_in[10];
    const float* Dp        = (const float*)d_in[11];
    const float* outproj_w = (const float*)d_in[12];
    const float* normf_w   = (const float*)d_in[13];
    const float* normf_b   = (const float*)d_in[14];
    const float* dw1       = (const float*)d_in[15];
    const float* db1       = (const float*)d_in[16];
    const float* dw2       = (const float*)d_in[17];
    const float* db2       = (const float*)d_in[18];
    float* out = (float*)d_out;

    float *h, *h2, *ln, *xz, *xc, *xd, *dtb, *y, *mo, *cat, *mid, *xwp;
    float *wip, *wop, *w1c, *w2c, *dwp; int* ord;
    cudaGetSymbolAddress((void**)&h,   g_h);
    cudaGetSymbolAddress((void**)&h2,  g_h2);
    cudaGetSymbolAddress((void**)&ln,  g_ln);
    cudaGetSymbolAddress((void**)&xz,  g_xz);
    cudaGetSymbolAddress((void**)&xc,  g_xc);
    cudaGetSymbolAddress((void**)&xd,  g_xd);
    cudaGetSymbolAddress((void**)&dtb, g_dt);
    cudaGetSymbolAddress((void**)&y,   g_y);
    cudaGetSymbolAddress((void**)&mo,  g_mo);
    cudaGetSymbolAddress((void**)&cat, g_cat);
    cudaGetSymbolAddress((void**)&mid, g_mid);
    cudaGetSymbolAddress((void**)&xwp, g_xwp);
    cudaGetSymbolAddress((void**)&wip, g_wip);
    cudaGetSymbolAddress((void**)&wop, g_wop);
    cudaGetSymbolAddress((void**)&w1c, g_w1c);
    cudaGetSymbolAddress((void**)&w2c, g_w2c);
    cudaGetSymbolAddress((void**)&dwp, g_dwp);
    cudaGetSymbolAddress((void**)&ord, g_ord);

    cudaFuncSetAttribute(k_gemm_tc128, cudaFuncAttributeMaxDynamicSharedMemorySize, G_SMEM_BYTES128);
    cudaFuncSetAttribute(k_gemm_tc64,  cudaFuncAttributeMaxDynamicSharedMemorySize, G_SMEM_BYTES64);

    const int EB3  = (ROWS3*ND  + 255)/256;
    const int EDI3 = (ROWS3*NDI + 255)/256;
    const int EC4  = (ROWS3*NDI/4 + 255)/256;

    // one-time per launch: weight conversions + padding
    k_cvt_all<<<(N_CVT + 255)/256, 256>>>(inproj_w, wip, outproj_w, wop, dw1, w1c, dw2, w2c);
    k_padxw<<<(12*XRP*NDI + 255)/256, 256>>>(xproj_w, xwp);
    k_paddw<<<(12*NDI*32 + 255)/256, 256>>>(dtproj_w, dwp);

    k_argsort<<<dim3(NB,3), 256>>>(center, ord);
    k_gather<<<EB3,256>>>(ginput, ord, h);
    k_ln<<<ROWS3/8,256>>>(h, norm_w, norm_b, ln, 4, 0);

    for (int blk = 0; blk < 4; blk++) {
        float* hin  = (blk & 1) ? h2 : h;
        float* hout = (blk & 1) ? h  : h2;

        k_gemm_tc128<<<dim3(2*NDI/128, ROWS3/128),256,G_SMEM_BYTES128>>>(
            ln, wip, xz, ND, ND, 2*NDI, nullptr, 0, 0, (size_t)2*NDI*ND, blk);

        k_conv<<<EC4,256>>>(xz, conv_w, conv_b, xc, blk);

        k_gemm_tc64<<<dim3(1, ROWS3/64),256,G_SMEM_BYTES64>>>(
            xc, xwp, xd, NDI, XRP, blk);

        // dt = softplus(xd[:, :32] @ dwp^T + db): K=32 GEMM, zero weight rows kill B/C cols
        k_gemm_tc128<<<dim3(NDI/128, ROWS3/128),256,G_SMEM_BYTES128>>>(
            xd, dwp, dtb, 32, XRP, NDI, dtproj_b, (size_t)NDI, 3, (size_t)NDI*32, blk);

        k_scan<<<dim3(NDI/64, NB, 3),512>>>(dtb, xc, xd, A_log, y, blk);

        k_gate<<<EDI3,256>>>(y, xc, Dp, xz, blk);

        k_gemm_tc128<<<dim3(ND/128, ROWS3/128),256,G_SMEM_BYTES128>>>(
            y, wop, mo, NDI, NDI, ND, nullptr, 0, 0, (size_t)ND*NDI, blk);

        if (blk < 3)
            k_resflip_ln<<<ROWS3/8,256>>>(hin, mo, norm_w, norm_b, hout, ln, 4, blk+1);
        else
            k_resflip_ln<<<ROWS3/8,256>>>(hin, mo, normf_w, normf_b, hout, ln, 1, 0);
    }

    k_scatter<<<EB3,256>>>(ln, ord, cat);

    // final MLP (M=4096 rows; mix evaluates to 0 within row range, wstride=0 -> weight offset 0)
    k_gemm_tc128<<<dim3(ND/128, ROWS/128),256,G_SMEM_BYTES128>>>(cat, w1c, mid, 3*ND, 3*ND, ND, db1, 0, 2, 0, 0);
    k_gemm_tc128<<<dim3(ND/128, ROWS/128),256,G_SMEM_BYTES128>>>(mid, w2c, out, ND,   ND,   ND, db2, 0, 1, 0, 0);
}